// round 5
// baseline (speedup 1.0000x reference)
#include <cuda_runtime.h>

#define NUM_BINS  512
#define NUM_NODES 128
#define N_PAIRS   1024
#define K_ELEMS   16384
#define NREP      32            // one histogram copy per lane -> conflict-free ATOMS

#define TASKS_PER_PAIR 8
#define CHUNK_F4   512          // float4 per task  (2048 elems)
#define TOTAL_TASKS (N_PAIRS * TASKS_PER_PAIR)   // 8192
#define HIST_BLOCKS   444       // 148 SMs * 3 CTAs (64KB smem) = one full wave
#define LOOKUP_BLOCKS 592       // 148 SMs * 4 CTAs             = one full wave

// Scratch (allocation-free rule: __device__ globals, zero-initialized at load)
__device__ float g_hist[NUM_NODES * NUM_BINS];
__device__ float g_tw[NUM_NODES];
__device__ float g_cdf[NUM_NODES * NUM_BINS];
// 2-byte lookup code per element: bin index if valid, 0xFFFF sentinel if not.
__device__ unsigned short g_code[(size_t)N_PAIRS * K_ELEMS];

// ---------------------------------------------------------------------------
// Kernel 1: persistent hist. Each block owns a contiguous range of 2048-elem
// tasks; the lane-replicated smem histogram is flushed only on pair change.
// g_hist/g_tw are zero on entry (zeroed by cdf_kernel after use).
// ---------------------------------------------------------------------------
extern __shared__ float sh_hist[];   // NUM_BINS * NREP floats = 64 KB

__device__ __forceinline__ void hist_process(
    float4 rv, float4 wv, int lane, float& wsum, unsigned short* cc)
{
    float rr[4] = {rv.x, rv.y, rv.z, rv.w};
    float ww[4] = {wv.x, wv.y, wv.z, wv.w};
    #pragma unroll
    for (int j = 0; j < 4; j++) {
        wsum += ww[j];
        // histogram bin: floor(r*512)   (*2^9 exact in fp32)
        int b = (int)floorf(rr[j] * 512.0f);
        if (b >= 0 && b < NUM_BINS)
            atomicAdd(&sh_hist[b * NREP + lane], ww[j]);    // bank == lane
        // lookup bin: floor(r*512 + 0.5); valid also requires w > 0
        int b2 = (int)floorf(rr[j] * 512.0f + 0.5f);
        bool valid = (b2 >= 0) && (b2 < NUM_BINS) && (ww[j] > 0.0f);
        cc[j] = valid ? (unsigned short)b2 : (unsigned short)0xFFFFu;
    }
}

__global__ __launch_bounds__(512) void hist_kernel(
    const float* __restrict__ res, const float* __restrict__ wgt,
    const int* __restrict__ src, const int* __restrict__ dst)
{
    __shared__ float sh_wsum;

    const int tid  = threadIdx.x;
    const int lane = tid & 31;

    int lo = (int)(((long long)blockIdx.x       * TOTAL_TASKS) / HIST_BLOCKS);
    int hi = (int)(((long long)(blockIdx.x + 1) * TOTAL_TASKS) / HIST_BLOCKS);

    int t = lo;
    while (t < hi) {
        const int p    = t / TASKS_PER_PAIR;
        const int tend = min(hi, (p + 1) * TASKS_PER_PAIR);

        // ---- zero the replicated histogram (prev segment readers are done:
        //      a __syncthreads follows every segment's reduction) ----
        float4* shz = (float4*)sh_hist;
        #pragma unroll
        for (int i = 0; i < (NUM_BINS * NREP / 4) / 512; i++)
            shz[tid + i * 512] = make_float4(0.f, 0.f, 0.f, 0.f);
        if (tid == 0) sh_wsum = 0.0f;
        __syncthreads();

        // ---- accumulate this segment's element range (pipelined) ----
        const float4* r4 = (const float4*)(res + (size_t)p * K_ELEMS);
        const float4* w4 = (const float4*)(wgt + (size_t)p * K_ELEMS);
        ushort4* c4 = (ushort4*)(g_code + (size_t)p * K_ELEMS);

        const int it0 = t - p * TASKS_PER_PAIR;     // first chunk in pair
        const int it1 = tend - p * TASKS_PER_PAIR;  // one past last

        float wsum = 0.0f;
        float4 rv = __ldcs(&r4[it0 * CHUNK_F4 + tid]);
        float4 wv = __ldcs(&w4[it0 * CHUNK_F4 + tid]);
        for (int it = it0; it < it1; it++) {
            float4 rn, wn;
            if (it + 1 < it1) {
                rn = __ldcs(&r4[(it + 1) * CHUNK_F4 + tid]);
                wn = __ldcs(&w4[(it + 1) * CHUNK_F4 + tid]);
            }
            unsigned short cc[4];
            hist_process(rv, wv, lane, wsum, cc);
            c4[it * CHUNK_F4 + tid] = make_ushort4(cc[0], cc[1], cc[2], cc[3]);
            rv = rn;
            wv = wn;
        }

        // warp-reduce wsum, one smem atomic per warp
        #pragma unroll
        for (int o = 16; o > 0; o >>= 1)
            wsum += __shfl_down_sync(0xffffffffu, wsum, o);
        if (lane == 0) atomicAdd(&sh_wsum, wsum);
        __syncthreads();

        // ---- reduce 32 copies -> 1 per bin, flush to global ----
        const int bin = tid;   // 512 threads == 512 bins
        float h = 0.0f;
        #pragma unroll
        for (int step = 0; step < NREP; step++)
            h += sh_hist[bin * NREP + ((lane + step) & 31)];   // conflict-free

        const int s = src[p];
        const int d = dst[p];
        atomicAdd(&g_hist[s * NUM_BINS + bin], h);
        atomicAdd(&g_hist[d * NUM_BINS + bin], h);
        if (tid == 0) {
            float ws = sh_wsum;
            atomicAdd(&g_tw[s], ws);
            atomicAdd(&g_tw[d], ws);
        }
        __syncthreads();   // protect smem before next segment's zeroing

        t = tend;
    }
}

// ---------------------------------------------------------------------------
// Kernel 2: cdf[node,:] = cumsum(hist[node,:] / (tw[node] + 1e-10)),
// then reset g_hist / g_tw to zero for the next invocation.
// ---------------------------------------------------------------------------
__global__ __launch_bounds__(512) void cdf_kernel() {
    __shared__ float warp_sums[16];

    const int node = blockIdx.x;
    const int tid  = threadIdx.x;

    const float inv_tw = 1.0f / (g_tw[node] + 1e-10f);
    float h = g_hist[node * NUM_BINS + tid];
    g_hist[node * NUM_BINS + tid] = 0.0f;     // reset for next call
    float x = h * inv_tw;

    #pragma unroll
    for (int o = 1; o < 32; o <<= 1) {
        float y = __shfl_up_sync(0xffffffffu, x, o);
        if ((tid & 31) >= o) x += y;
    }
    if ((tid & 31) == 31) warp_sums[tid >> 5] = x;
    __syncthreads();

    if (tid == 0) g_tw[node] = 0.0f;          // all reads of g_tw done pre-sync

    if (tid < 16) {
        float s = warp_sums[tid];
        #pragma unroll
        for (int o = 1; o < 16; o <<= 1) {
            float y = __shfl_up_sync(0x0000ffffu, s, o);
            if (tid >= o) s += y;
        }
        warp_sums[tid] = s;
    }
    __syncthreads();

    float base = (tid >= 32) ? warp_sums[(tid >> 5) - 1] : 0.0f;
    g_cdf[node * NUM_BINS + tid] = x + base;
}

// ---------------------------------------------------------------------------
// Kernel 3: persistent lookup via cached 2-byte codes. Contiguous task
// ranges; cdf rows reloaded into smem only on pair change.
// Output layout: out[0 : N*K) = src_cdf, out[N*K : 2*N*K) = dst_cdf.
// ---------------------------------------------------------------------------
__device__ __forceinline__ void lookup_process(
    ushort4 cv, const float* sh_s, const float* sh_d, float4& os, float4& od)
{
    unsigned short cc[4] = {cv.x, cv.y, cv.z, cv.w};
    float* pos = (float*)&os;
    float* pod = (float*)&od;
    #pragma unroll
    for (int j = 0; j < 4; j++) {
        unsigned short c = cc[j];
        if (c < NUM_BINS) {
            pos[j] = sh_s[c];
            pod[j] = sh_d[c];
        } else {
            pos[j] = 2.0f;
            pod[j] = 2.0f;
        }
    }
}

__global__ __launch_bounds__(512) void lookup_kernel(
    const int* __restrict__ src, const int* __restrict__ dst,
    float* __restrict__ out)
{
    __shared__ float sh_s[NUM_BINS];
    __shared__ float sh_d[NUM_BINS];

    const int tid = threadIdx.x;

    int lo = (int)(((long long)blockIdx.x       * TOTAL_TASKS) / LOOKUP_BLOCKS);
    int hi = (int)(((long long)(blockIdx.x + 1) * TOTAL_TASKS) / LOOKUP_BLOCKS);

    int t = lo;
    while (t < hi) {
        const int p    = t / TASKS_PER_PAIR;
        const int tend = min(hi, (p + 1) * TASKS_PER_PAIR);

        __syncthreads();   // previous segment's smem readers are done
        const int s = src[p];
        const int d = dst[p];
        sh_s[tid] = g_cdf[s * NUM_BINS + tid];   // 512 threads == 512 bins
        sh_d[tid] = g_cdf[d * NUM_BINS + tid];
        __syncthreads();

        const ushort4* c4 = (const ushort4*)(g_code + (size_t)p * K_ELEMS);
        float4* o_s = (float4*)(out + (size_t)p * K_ELEMS);
        float4* o_d = (float4*)(out + (size_t)(N_PAIRS + p) * K_ELEMS);

        const int it0 = t - p * TASKS_PER_PAIR;
        const int it1 = tend - p * TASKS_PER_PAIR;

        ushort4 cv = c4[it0 * CHUNK_F4 + tid];
        for (int it = it0; it < it1; it++) {
            ushort4 cn;
            if (it + 1 < it1) cn = c4[(it + 1) * CHUNK_F4 + tid];
            float4 os, od;
            lookup_process(cv, sh_s, sh_d, os, od);
            __stcs(&o_s[it * CHUNK_F4 + tid], os);   // streaming: never re-read
            __stcs(&o_d[it * CHUNK_F4 + tid], od);
            cv = cn;
        }

        t = tend;
    }
}

// ---------------------------------------------------------------------------
extern "C" void kernel_launch(void* const* d_in, const int* in_sizes, int n_in,
                              void* d_out, int out_size)
{
    const float* res = (const float*)d_in[0];
    const float* wgt = (const float*)d_in[1];
    const int*   src = (const int*)d_in[2];
    const int*   dst = (const int*)d_in[3];
    float*       out = (float*)d_out;

    const int smem = NUM_BINS * NREP * sizeof(float);   // 64 KB
    cudaFuncSetAttribute(hist_kernel,
                         cudaFuncAttributeMaxDynamicSharedMemorySize, smem);

    hist_kernel<<<HIST_BLOCKS, 512, smem>>>(res, wgt, src, dst);
    cdf_kernel<<<NUM_NODES, 512>>>();
    lookup_kernel<<<LOOKUP_BLOCKS, 512>>>(src, dst, out);
}

// round 6
// speedup vs baseline: 1.1557x; 1.1557x over previous
#include <cuda_runtime.h>

#define NUM_BINS  512
#define NUM_NODES 128
#define N_PAIRS   1024
#define K_ELEMS   16384
#define NREP      32            // one histogram copy per lane -> conflict-free ATOMS

#define TASKS_PER_PAIR 8
#define CHUNK_F4   512          // float4 per task  (2048 elems)
#define TOTAL_TASKS (N_PAIRS * TASKS_PER_PAIR)   // 8192
#define HIST_BLOCKS   444       // 148 SMs * 3 CTAs (64KB smem) = one full wave
#define LOOKUP_BLOCKS 592       // 148 SMs * 4 CTAs             = one full wave

// Scratch (allocation-free rule: __device__ globals, zero-initialized at load)
__device__ float g_hist[NUM_NODES * NUM_BINS];
__device__ float g_tw[NUM_NODES];
__device__ float g_cdf[NUM_NODES * NUM_BINS];
// 2-byte lookup code per element: bin index if valid, 0xFFFF sentinel if not.
__device__ unsigned short g_code[(size_t)N_PAIRS * K_ELEMS];

// ---------------------------------------------------------------------------
// Kernel 1: persistent hist, register-budgeted to 3 CTAs/SM (42-reg cap).
// Each block owns a contiguous range of 2048-elem tasks; the lane-replicated
// smem histogram is flushed only on pair change. Simple load->process loop
// (no deep pipeline): 48 warps/SM hide the LDG latency.
// g_hist/g_tw are zero on entry (zeroed by cdf_kernel after use).
// ---------------------------------------------------------------------------
extern __shared__ float sh_hist[];   // NUM_BINS * NREP floats = 64 KB

__global__ void __launch_bounds__(512, 3) hist_kernel(
    const float* __restrict__ res, const float* __restrict__ wgt,
    const int* __restrict__ src, const int* __restrict__ dst)
{
    __shared__ float sh_wsum;

    const int tid  = threadIdx.x;
    const int lane = tid & 31;

    int lo = (int)(((long long)blockIdx.x       * TOTAL_TASKS) / HIST_BLOCKS);
    int hi = (int)(((long long)(blockIdx.x + 1) * TOTAL_TASKS) / HIST_BLOCKS);

    int t = lo;
    while (t < hi) {
        const int p    = t / TASKS_PER_PAIR;
        const int tend = min(hi, (p + 1) * TASKS_PER_PAIR);

        // ---- zero the replicated histogram ----
        float4* shz = (float4*)sh_hist;
        #pragma unroll
        for (int i = 0; i < (NUM_BINS * NREP / 4) / 512; i++)
            shz[tid + i * 512] = make_float4(0.f, 0.f, 0.f, 0.f);
        if (tid == 0) sh_wsum = 0.0f;
        __syncthreads();

        // ---- accumulate this segment's element range ----
        const float4* r4 = (const float4*)(res + (size_t)p * K_ELEMS);
        const float4* w4 = (const float4*)(wgt + (size_t)p * K_ELEMS);
        ushort4* c4 = (ushort4*)(g_code + (size_t)p * K_ELEMS);

        const int i0 = (t    - p * TASKS_PER_PAIR) * CHUNK_F4;
        const int i1 = (tend - p * TASKS_PER_PAIR) * CHUNK_F4;

        float wsum = 0.0f;
        for (int i = i0 + tid; i < i1; i += 512) {
            float4 rv = __ldcs(&r4[i]);   // read-once: stream past L2
            float4 wv = __ldcs(&w4[i]);
            float rr[4] = {rv.x, rv.y, rv.z, rv.w};
            float ww[4] = {wv.x, wv.y, wv.z, wv.w};
            unsigned short cc[4];
            #pragma unroll
            for (int j = 0; j < 4; j++) {
                wsum += ww[j];
                float x = rr[j] * 512.0f;          // *2^9 exact in fp32
                int b  = (int)floorf(x);           // histogram bin
                if (b >= 0 && b < NUM_BINS)
                    atomicAdd(&sh_hist[b * NREP + lane], ww[j]);  // bank==lane
                int b2 = (int)floorf(x + 0.5f);    // lookup bin
                bool valid = (b2 >= 0) && (b2 < NUM_BINS) && (ww[j] > 0.0f);
                cc[j] = valid ? (unsigned short)b2 : (unsigned short)0xFFFFu;
            }
            c4[i] = make_ushort4(cc[0], cc[1], cc[2], cc[3]);
        }

        // warp-reduce wsum, one smem atomic per warp
        #pragma unroll
        for (int o = 16; o > 0; o >>= 1)
            wsum += __shfl_down_sync(0xffffffffu, wsum, o);
        if (lane == 0) atomicAdd(&sh_wsum, wsum);
        __syncthreads();

        // ---- reduce 32 copies -> 1 per bin, flush to global ----
        const int bin = tid;   // 512 threads == 512 bins
        float h = 0.0f;
        #pragma unroll
        for (int step = 0; step < NREP; step++)
            h += sh_hist[bin * NREP + ((lane + step) & 31)];   // conflict-free

        const int s = src[p];
        const int d = dst[p];
        atomicAdd(&g_hist[s * NUM_BINS + bin], h);
        atomicAdd(&g_hist[d * NUM_BINS + bin], h);
        if (tid == 0) {
            float ws = sh_wsum;
            atomicAdd(&g_tw[s], ws);
            atomicAdd(&g_tw[d], ws);
        }
        __syncthreads();   // protect smem before next segment's zeroing

        t = tend;
    }
}

// ---------------------------------------------------------------------------
// Kernel 2: cdf[node,:] = cumsum(hist[node,:] / (tw[node] + 1e-10)),
// then reset g_hist / g_tw to zero for the next invocation.
// ---------------------------------------------------------------------------
__global__ __launch_bounds__(512) void cdf_kernel() {
    __shared__ float warp_sums[16];

    const int node = blockIdx.x;
    const int tid  = threadIdx.x;

    const float inv_tw = 1.0f / (g_tw[node] + 1e-10f);
    float h = g_hist[node * NUM_BINS + tid];
    g_hist[node * NUM_BINS + tid] = 0.0f;     // reset for next call
    float x = h * inv_tw;

    #pragma unroll
    for (int o = 1; o < 32; o <<= 1) {
        float y = __shfl_up_sync(0xffffffffu, x, o);
        if ((tid & 31) >= o) x += y;
    }
    if ((tid & 31) == 31) warp_sums[tid >> 5] = x;
    __syncthreads();

    if (tid == 0) g_tw[node] = 0.0f;          // all reads of g_tw done pre-sync

    if (tid < 16) {
        float s = warp_sums[tid];
        #pragma unroll
        for (int o = 1; o < 16; o <<= 1) {
            float y = __shfl_up_sync(0x0000ffffu, s, o);
            if (tid >= o) s += y;
        }
        warp_sums[tid] = s;
    }
    __syncthreads();

    float base = (tid >= 32) ? warp_sums[(tid >> 5) - 1] : 0.0f;
    g_cdf[node * NUM_BINS + tid] = x + base;
}

// ---------------------------------------------------------------------------
// Kernel 3: persistent lookup via cached 2-byte codes, 4 CTAs/SM (32-reg cap).
// Contiguous task ranges; cdf rows reloaded into smem only on pair change.
// Output layout: out[0 : N*K) = src_cdf, out[N*K : 2*N*K) = dst_cdf.
// ---------------------------------------------------------------------------
__global__ void __launch_bounds__(512, 4) lookup_kernel(
    const int* __restrict__ src, const int* __restrict__ dst,
    float* __restrict__ out)
{
    __shared__ float sh_s[NUM_BINS];
    __shared__ float sh_d[NUM_BINS];

    const int tid = threadIdx.x;

    int lo = (int)(((long long)blockIdx.x       * TOTAL_TASKS) / LOOKUP_BLOCKS);
    int hi = (int)(((long long)(blockIdx.x + 1) * TOTAL_TASKS) / LOOKUP_BLOCKS);

    int t = lo;
    while (t < hi) {
        const int p    = t / TASKS_PER_PAIR;
        const int tend = min(hi, (p + 1) * TASKS_PER_PAIR);

        __syncthreads();   // previous segment's smem readers are done
        const int s = src[p];
        const int d = dst[p];
        sh_s[tid] = g_cdf[s * NUM_BINS + tid];   // 512 threads == 512 bins
        sh_d[tid] = g_cdf[d * NUM_BINS + tid];
        __syncthreads();

        const ushort4* c4 = (const ushort4*)(g_code + (size_t)p * K_ELEMS);
        float4* o_s = (float4*)(out + (size_t)p * K_ELEMS);
        float4* o_d = (float4*)(out + (size_t)(N_PAIRS + p) * K_ELEMS);

        const int i0 = (t    - p * TASKS_PER_PAIR) * CHUNK_F4;
        const int i1 = (tend - p * TASKS_PER_PAIR) * CHUNK_F4;

        // depth-1 prefetch of the 8-byte code vector (cheap: 2 regs)
        ushort4 cv = c4[i0 + tid];
        for (int i = i0 + tid; i < i1; i += 512) {
            ushort4 cn;
            if (i + 512 < i1) cn = c4[i + 512];
            unsigned short cc[4] = {cv.x, cv.y, cv.z, cv.w};
            float4 os, od;
            float* pos = (float*)&os;
            float* pod = (float*)&od;
            #pragma unroll
            for (int j = 0; j < 4; j++) {
                unsigned short c = cc[j];
                if (c < NUM_BINS) {
                    pos[j] = sh_s[c];
                    pod[j] = sh_d[c];
                } else {
                    pos[j] = 2.0f;
                    pod[j] = 2.0f;
                }
            }
            __stcs(&o_s[i], os);   // streaming: never re-read
            __stcs(&o_d[i], od);
            cv = cn;
        }

        t = tend;
    }
}

// ---------------------------------------------------------------------------
extern "C" void kernel_launch(void* const* d_in, const int* in_sizes, int n_in,
                              void* d_out, int out_size)
{
    const float* res = (const float*)d_in[0];
    const float* wgt = (const float*)d_in[1];
    const int*   src = (const int*)d_in[2];
    const int*   dst = (const int*)d_in[3];
    float*       out = (float*)d_out;

    const int smem = NUM_BINS * NREP * sizeof(float);   // 64 KB
    cudaFuncSetAttribute(hist_kernel,
                         cudaFuncAttributeMaxDynamicSharedMemorySize, smem);

    hist_kernel<<<HIST_BLOCKS, 512, smem>>>(res, wgt, src, dst);
    cdf_kernel<<<NUM_NODES, 512>>>();
    lookup_kernel<<<LOOKUP_BLOCKS, 512>>>(src, dst, out);
}